// round 3
// baseline (speedup 1.0000x reference)
#include <cuda_runtime.h>
#include <cstdint>

#define NB   128
#define NTH  256

// SMEM float offsets
#define W_OFF    0        // 26624 floats: dup weights [13][128 k][16]
#define IN_OFF   26624    // 16384: double-buffered input chunk [2][128][64]
#define RED_OFF  43008    // 8448: reduction 32 rows x 264
#define XS_OFF   51456    // 768
#define BIAS_OFF 52224    // 16
#define SMEM_FLOATS 52240
#define SMEM_BYTES  (SMEM_FLOATS*4)

__device__ float    g_rbuf[2][1536*64];   // rates, [k][b]
__device__ float    g_XT[499*128*64];     // X transposed/padded: [s][d(128)][b]
__device__ float    g_Rm1[499*512*64];    // r_m1 history [s][k][b]
__device__ unsigned g_bar_count;
__device__ unsigned g_bar_gen;

__device__ __forceinline__ void cp16(float* sdst, const float* gsrc) {
    unsigned s = (unsigned)__cvta_generic_to_shared(sdst);
    asm volatile("cp.async.cg.shared.global [%0], [%1], 16;\n" :: "r"(s), "l"(gsrc) : "memory");
}

__device__ __forceinline__ void stage(float* dst, const float* src, int tid) {
    for (int i = tid; i < 2048; i += NTH) cp16(dst + i*4, src + i*4);
    asm volatile("cp.async.commit_group;\n" ::: "memory");
}

__device__ __forceinline__ void grid_barrier() {
    __syncthreads();
    if (threadIdx.x == 0) {
        __threadfence();
        unsigned old = *(volatile unsigned*)&g_bar_gen;
        if (atomicAdd(&g_bar_count, 1u) == NB - 1u) {
            atomicExch(&g_bar_count, 0u);
            __threadfence();
            atomicAdd(&g_bar_gen, 1u);
        } else {
            while (*(volatile unsigned*)&g_bar_gen == old) { }
        }
    }
    __syncthreads();
}

// Packed-FFMA2 chunk: 16 k-iters, acc[bp*4+jj] (bp = batch pair, jj = col)
__device__ __forceinline__ void chunk_fma2(uint64_t (&acc)[8], unsigned rbase, unsigned wbase) {
    uint64_t rv[2][2], wv[2][4];
    asm volatile("ld.shared.v2.b64 {%0,%1},[%2];" : "=l"(rv[0][0]), "=l"(rv[0][1]) : "r"(rbase));
    asm volatile("ld.shared.v2.b64 {%0,%1},[%2];" : "=l"(wv[0][0]), "=l"(wv[0][1]) : "r"(wbase));
    asm volatile("ld.shared.v2.b64 {%0,%1},[%2];" : "=l"(wv[0][2]), "=l"(wv[0][3]) : "r"(wbase + 16));
    #pragma unroll
    for (int t = 0; t < 16; t++) {
        const int cu = t & 1, nx = cu ^ 1;
        if (t < 15) {
            unsigned ra = rbase + (unsigned)(t+1)*256u;
            unsigned wa = wbase + (unsigned)(t+1)*64u;
            asm volatile("ld.shared.v2.b64 {%0,%1},[%2];" : "=l"(rv[nx][0]), "=l"(rv[nx][1]) : "r"(ra));
            asm volatile("ld.shared.v2.b64 {%0,%1},[%2];" : "=l"(wv[nx][0]), "=l"(wv[nx][1]) : "r"(wa));
            asm volatile("ld.shared.v2.b64 {%0,%1},[%2];" : "=l"(wv[nx][2]), "=l"(wv[nx][3]) : "r"(wa + 16));
        }
        #pragma unroll
        for (int bp = 0; bp < 2; bp++)
            #pragma unroll
            for (int jj = 0; jj < 4; jj++)
                asm volatile("fma.rn.f32x2 %0,%1,%2,%0;"
                             : "+l"(acc[bp*4+jj]) : "l"(rv[cu][bp]), "l"(wv[cu][jj]));
    }
}

__global__ void __launch_bounds__(NTH, 1)
rnn_kernel(const float* __restrict__ X,
           const float* __restrict__ W_rec_m1, const float* __restrict__ W_rec_pmd,
           const float* __restrict__ W_rec_s1,
           const float* __restrict__ b_m1, const float* __restrict__ b_pmd,
           const float* __restrict__ b_s1,
           const float* __restrict__ W_pmd_m1, const float* __restrict__ W_s1_m1,
           const float* __restrict__ W_m1_pmd,
           const float* __restrict__ W_in_pmd, const float* __restrict__ W_in_s1,
           const float* __restrict__ W_out,
           float* __restrict__ out)
{
    extern __shared__ float sm[];
    const int tid = threadIdx.x;
    const int g   = blockIdx.x;
    float* w_s    = sm + W_OFF;
    float* in_s   = sm + IN_OFF;
    float* red_s  = sm + RED_OFF;
    float* xs     = sm + XS_OFF;
    float* bias_s = sm + BIAS_OFF;
    const int j0  = 4*g;
    const unsigned smb = (unsigned)__cvta_generic_to_shared(sm);
    const unsigned in_b  = smb + IN_OFF*4u;
    const unsigned w_b   = smb + W_OFF*4u;

    // ---- phase 0: init globals ----
    for (int i = g*NTH + tid; i < 2*1536*64; i += NB*NTH) ((float*)g_rbuf)[i] = 0.f;
    for (int i = g*NTH + tid; i < 499*128*64; i += NB*NTH) {
        int b = i & 63, d = (i >> 6) & 127, s = i >> 13;
        g_XT[i] = (d < 100) ? X[((s+1)*64 + b)*100 + d] : 0.f;
    }

    // ---- duplicated weights into SMEM: w_s[c][k][16], float16 = w0,w0,w1,w1,w2,w2,w3,w3 per jg ----
    // c0-3 src r_m1:  jg0=W_m1_pmd(->pmd) jg1=W_rec_m1(->m1)
    // c4-7 src r_pmd: jg0=W_rec_pmd(->pmd) jg1=W_pmd_m1(->m1)
    // c8-11 src r_s1: jg0=W_s1_m1(->m1)   jg1=W_rec_s1(->s1)
    // c12  src Xt:    jg0=W_in_pmd(->pmd) jg1=W_in_s1(->s1)
    for (int idx = tid; idx < 26624; idx += NTH) {
        int c = idx >> 11, rem = idx & 2047, k = rem >> 4, slot = rem & 15;
        int jgq = slot >> 3, jj = (slot >> 1) & 3;
        float v;
        if (c < 4) { int kk = c*128 + k;
            v = jgq ? W_rec_m1[(j0+jj)*512 + kk] : W_m1_pmd[(j0+jj)*512 + kk];
        } else if (c < 8) { int kk = (c-4)*128 + k;
            v = jgq ? W_pmd_m1[(j0+jj)*512 + kk] : W_rec_pmd[(j0+jj)*512 + kk];
        } else if (c < 12) { int kk = (c-8)*128 + k;
            v = jgq ? W_rec_s1[(j0+jj)*512 + kk] : W_s1_m1[(j0+jj)*512 + kk];
        } else {
            v = (k < 100) ? (jgq ? W_in_s1[(j0+jj)*100 + k] : W_in_pmd[(j0+jj)*100 + k]) : 0.f;
        }
        w_s[idx] = v;
    }
    if (tid < 12) {
        int jj = tid & 3;
        bias_s[tid] = (tid < 4) ? b_m1[j0+jj] : ((tid < 8) ? b_pmd[j0+jj] : b_s1[j0+jj]);
    }
    for (int i = tid; i < 768; i += NTH) xs[i] = 0.f;

    grid_barrier();

    const int ks   = tid >> 5;
    const int lane = tid & 31;
    const int jg   = lane >> 4;
    const int b0   = (lane & 15) * 4;
    const unsigned rth = (unsigned)(b0*4 + ks*4096);   // per-thread offset in a chunk buffer
    const unsigned wth = (unsigned)(jg*32 + ks*1024);  // per-thread offset in a weight chunk

    // ---- the 499-step scan ----
    for (int s = 0; s < 499; s++) {
        const int cur = s & 1;
        const float* rb = g_rbuf[cur];

        stage(in_s, rb, tid);
        asm volatile("cp.async.wait_group 0;\n" ::: "memory");
        __syncthreads();

        uint64_t accP[8], accS[8], accX[8];
        #pragma unroll
        for (int i = 0; i < 8; i++) { accP[i] = 0ull; accS[i] = 0ull; accX[i] = 0ull; }

        for (int c = 0; c < 8; c++) {
            stage(in_s + ((c+1)&1)*8192, rb + (c+1)*8192, tid);
            chunk_fma2(accP, in_b + (unsigned)((c&1)*32768) + rth, w_b + (unsigned)(c*8192) + wth);
            asm volatile("cp.async.wait_group 0;\n" ::: "memory");
            __syncthreads();
        }
        for (int c = 8; c < 12; c++) {
            const float* src = (c < 11) ? (rb + (c+1)*8192) : (g_XT + s*8192);
            stage(in_s + ((c+1)&1)*8192, src, tid);
            chunk_fma2(accS, in_b + (unsigned)((c&1)*32768) + rth, w_b + (unsigned)(c*8192) + wth);
            asm volatile("cp.async.wait_group 0;\n" ::: "memory");
            __syncthreads();
        }
        chunk_fma2(accX, in_b + 0u + rth, w_b + 12u*8192u + wth);

        // merge accX: jg0 -> pmd(accP), jg1 -> s1(accS)
        if (jg == 0) {
            #pragma unroll
            for (int i = 0; i < 8; i++)
                asm volatile("add.rn.f32x2 %0,%0,%1;" : "+l"(accP[i]) : "l"(accX[i]));
        } else {
            #pragma unroll
            for (int i = 0; i < 8; i++)
                asm volatile("add.rn.f32x2 %0,%0,%1;" : "+l"(accS[i]) : "l"(accX[i]));
        }

        // dump partials, layout red_s[row][jj*64 + b], row stride 264
        {
            const int rowP = 4*ks + 2*jg, rowS = rowP + 1;
            #pragma unroll
            for (int bp = 0; bp < 2; bp++) {
                int b = b0 + bp*2;
                #pragma unroll
                for (int jj = 0; jj < 4; jj++) {
                    *(uint64_t*)(red_s + rowP*264 + jj*64 + b) = accP[bp*4+jj];
                    *(uint64_t*)(red_s + rowS*264 + jj*64 + b) = accS[bp*4+jj];
                }
            }
        }
        __syncthreads();

        // reduce across 8 K-slice warps, leaky update, tanh, publish
        float* rnew = g_rbuf[cur ^ 1];
        for (int idx = tid; idx < 768; idx += NTH) {
            int col = idx >> 6, b = idx & 63, jj = col & 3;
            int e = jj*64 + b;
            float sum = 0.f;
            if (col < 4) {            // m1: rows 4q+1 (jg0-S), 4q+2 (jg1-P)
                #pragma unroll
                for (int q = 0; q < 8; q++)
                    sum += red_s[(4*q+1)*264 + e] + red_s[(4*q+2)*264 + e];
            } else if (col < 8) {     // pmd: rows 4q (jg0-P)
                #pragma unroll
                for (int q = 0; q < 8; q++) sum += red_s[(4*q+0)*264 + e];
            } else {                  // s1: rows 4q+3 (jg1-S)
                #pragma unroll
                for (int q = 0; q < 8; q++) sum += red_s[(4*q+3)*264 + e];
            }
            float x = xs[idx];
            x = 0.9f*x + 0.1f*(sum + bias_s[col]);
            xs[idx] = x;
            float r = tanhf(x);
            int grow = (col < 4) ? (j0 + col)
                     : (col < 8) ? (512 + j0 + col - 4)
                                 : (1024 + j0 + col - 8);
            rnew[grow*64 + b] = r;
            if (col < 4) g_Rm1[(s*512 + j0 + col)*64 + b] = r;
        }
        grid_barrier();
    }

    // ---- epilogue: out[t][b][o] = sum_k Rm1[t][k][b] * W_out[o][k] ----
    for (int i = tid; i < 5120; i += NTH) w_s[i] = W_out[i];
    for (int t = g; t < 499; t += NB) {
        float acc3[3] = {0.f, 0.f, 0.f};
        for (int h = 0; h < 2; h++) {
            __syncthreads();
            const float4* src = (const float4*)(g_Rm1 + (t*512 + h*256)*64);
            for (int i = tid; i < 4096; i += NTH) ((float4*)in_s)[i] = src[i];
            __syncthreads();
            #pragma unroll
            for (int pi = 0; pi < 3; pi++) {
                int p = tid + pi*256;
                if (p < 640) {
                    int o = p >> 6, b = p & 63;
                    float sv = 0.f;
                    #pragma unroll 8
                    for (int k = 0; k < 256; k++)
                        sv += in_s[k*64 + b] * w_s[o*512 + h*256 + k];
                    acc3[pi] += sv;
                }
            }
        }
        #pragma unroll
        for (int pi = 0; pi < 3; pi++) {
            int p = tid + pi*256;
            if (p < 640) {
                int o = p >> 6, b = p & 63;
                out[t*640 + b*10 + o] = acc3[pi];
            }
        }
    }
}

extern "C" void kernel_launch(void* const* d_in, const int* in_sizes, int n_in,
                              void* d_out, int out_size) {
    cudaFuncSetAttribute(rnn_kernel, cudaFuncAttributeMaxDynamicSharedMemorySize, SMEM_BYTES);
    rnn_kernel<<<NB, NTH, SMEM_BYTES>>>(
        (const float*)d_in[0],  (const float*)d_in[1],  (const float*)d_in[2],
        (const float*)d_in[3],  (const float*)d_in[4],  (const float*)d_in[5],
        (const float*)d_in[6],  (const float*)d_in[7],  (const float*)d_in[8],
        (const float*)d_in[9],  (const float*)d_in[10], (const float*)d_in[11],
        (const float*)d_in[12], (float*)d_out);
}